// round 15
// baseline (speedup 1.0000x reference)
#include <cuda_runtime.h>
#include <cuda_fp16.h>
#include <cstdint>

#define Bv 8
#define Tv 512
#define Mv 16
#define Dv 128
#define Pv 256
#define Hv 8
#define Ev 32
#define ROWS (Bv*Tv*Mv)   // 65536
#define MP 4096           // Mv*Pv: element stride between consecutive t (original layout)

// Q in [bm][t][P] layout; K/V COMPACTED per (b,m) in [bm][key][P] layout.
__device__ half g_qh[(size_t)ROWS * Pv];
__device__ half g_ql[(size_t)ROWS * Pv];
__device__ half g_kh[(size_t)ROWS * Pv];
__device__ half g_kl[(size_t)ROWS * Pv];
__device__ half g_vh[(size_t)ROWS * Pv];
__device__ half g_vl[(size_t)ROWS * Pv];
// Pre-split GEMM inputs: A (inp) hi/lo, W transposed [which][c][k] hi/lo.
__device__ half g_ah[(size_t)ROWS * Dv];
__device__ half g_al[(size_t)ROWS * Dv];
__device__ half g_wh[3 * Pv * Dv];
__device__ half g_wl[3 * Pv * Dv];
// Compaction metadata
__device__ int g_pos[Bv * Mv * Tv];   // compacted pos per (bm,t); -1 if masked
__device__ int g_nv[Bv * Mv];         // valid count per (bm)

__device__ __forceinline__ void split2(float x, half& hi, half& lo) {
    hi = __float2half_rn(x);
    lo = __float2half_rn(x - __half2float(hi));
}
__device__ __forceinline__ void splitpack(float x, float y, uint32_t& hi, uint32_t& lo) {
    half hx, lx, hy, ly;
    split2(x, hx, lx);
    split2(y, hy, ly);
    __half2 h = __halves2half2(hx, hy);
    __half2 l = __halves2half2(lx, ly);
    hi = *(uint32_t*)&h;
    lo = *(uint32_t*)&l;
}
__device__ __forceinline__ void mma16816(float* c, const uint32_t* a, const uint32_t* b) {
    asm volatile(
        "mma.sync.aligned.m16n8k16.row.col.f32.f16.f16.f32 "
        "{%0,%1,%2,%3}, {%4,%5,%6,%7}, {%8,%9}, {%0,%1,%2,%3};\n"
        : "+f"(c[0]), "+f"(c[1]), "+f"(c[2]), "+f"(c[3])
        : "r"(a[0]), "r"(a[1]), "r"(a[2]), "r"(a[3]), "r"(b[0]), "r"(b[1]));
}
__device__ __forceinline__ void ldsm4(uint32_t* r, uint32_t a) {
    asm volatile("ldmatrix.sync.aligned.m8n8.x4.shared.b16 {%0,%1,%2,%3}, [%4];"
        : "=r"(r[0]), "=r"(r[1]), "=r"(r[2]), "=r"(r[3]) : "r"(a));
}
__device__ __forceinline__ void ldsm4t(uint32_t* r, uint32_t a) {
    asm volatile("ldmatrix.sync.aligned.m8n8.x4.trans.shared.b16 {%0,%1,%2,%3}, [%4];"
        : "=r"(r[0]), "=r"(r[1]), "=r"(r[2]), "=r"(r[3]) : "r"(a));
}
__device__ __forceinline__ uint32_t sm_u32(const void* p) {
    return (uint32_t)__cvta_generic_to_shared(p);
}
__device__ __forceinline__ void cp16(uint32_t dst, const void* src) {
    asm volatile("cp.async.cg.shared.global [%0], [%1], 16;" :: "r"(dst), "l"(src));
}
__device__ __forceinline__ void cp_commit() {
    asm volatile("cp.async.commit_group;");
}
template<int N>
__device__ __forceinline__ void cp_wait() {
    asm volatile("cp.async.wait_group %0;" :: "n"(N));
}

// ===========================================================================
// Prep kernels
// ===========================================================================
__global__ __launch_bounds__(256) void prep_a(const float* __restrict__ inp)
{
    size_t idx = (size_t)blockIdx.x * 256 + threadIdx.x;
    float4 a = *(const float4*)&inp[idx * 4];
    uint32_t h0, l0, h1, l1;
    splitpack(a.x, a.y, h0, l0);
    splitpack(a.z, a.w, h1, l1);
    *(uint32_t*)&g_ah[idx * 4]     = h0;
    *(uint32_t*)&g_ah[idx * 4 + 2] = h1;
    *(uint32_t*)&g_al[idx * 4]     = l0;
    *(uint32_t*)&g_al[idx * 4 + 2] = l1;
}

__global__ __launch_bounds__(256) void prep_w(
    const float* __restrict__ Wq, const float* __restrict__ Wk, const float* __restrict__ Wv)
{
    int t = blockIdx.x * 256 + threadIdx.x;
    int which = t / 8192;
    int rem = t - which * 8192;
    int c  = rem >> 5;
    int k4 = (rem & 31) * 4;
    const float* W = (which == 0) ? Wq : (which == 1) ? Wk : Wv;
    float w0 = W[(size_t)(k4 + 0) * Pv + c];
    float w1 = W[(size_t)(k4 + 1) * Pv + c];
    float w2 = W[(size_t)(k4 + 2) * Pv + c];
    float w3 = W[(size_t)(k4 + 3) * Pv + c];
    uint32_t h0, l0, h1, l1;
    splitpack(w0, w1, h0, l0);
    splitpack(w2, w3, h1, l1);
    size_t off = ((size_t)which * Pv + c) * Dv + k4;
    *(uint32_t*)&g_wh[off]     = h0;
    *(uint32_t*)&g_wh[off + 2] = h1;
    *(uint32_t*)&g_wl[off]     = l0;
    *(uint32_t*)&g_wl[off + 2] = l1;
}

// Mask prefix scan per (b,m) + zero-pad compacted K/V tail to tile boundary.
__global__ __launch_bounds__(512) void prep_mask(const int* __restrict__ mask)
{
    __shared__ int wsum[16], woff[16], total_s;
    const int bm = blockIdx.x;
    const int b = bm >> 4, m = bm & 15;
    const int t = threadIdx.x;
    const int lane = t & 31, wid = t >> 5;

    int valid = mask[(size_t)(b * Tv + t) * Mv + m] ? 1 : 0;
    unsigned bal = __ballot_sync(0xffffffffu, valid);
    int wpre = __popc(bal & ((1u << lane) - 1u));
    if (lane == 31) wsum[wid] = wpre + valid;
    __syncthreads();
    if (t == 0) {
        int s = 0;
        for (int i = 0; i < 16; i++) { woff[i] = s; s += wsum[i]; }
        total_s = s;
    }
    __syncthreads();
    const int total = total_s;
    int pos = woff[wid] + wpre;
    g_pos[bm * Tv + t] = valid ? pos : -1;
    if (t == 0) g_nv[bm] = total;

    int padend = (total + 63) & ~63;
    int npad = padend - total;
    uint4 z = make_uint4(0, 0, 0, 0);
    for (int i = t; i < npad * (Pv / 8); i += 512) {
        int rr = total + i / (Pv / 8);
        int e8 = (i % (Pv / 8)) * 8;
        size_t off = ((size_t)bm * Tv + rr) * Pv + e8;
        *(uint4*)&g_kh[off] = z;
        *(uint4*)&g_kl[off] = z;
        *(uint4*)&g_vh[off] = z;
        *(uint4*)&g_vl[off] = z;
    }
}

// ===========================================================================
// QKV GEMM: 128x64 tile, full K=128 staged once, 2 blocks/SM.
// smem: A hi/lo [128][136] + W hi/lo [64][136] = 104448 B.
// ===========================================================================
#define GLD2 136
#define A_AR (128 * GLD2)   // halfs per A array
#define W_AR (64 * GLD2)    // halfs per W array
#define GEMM_SMEM ((2 * A_AR + 2 * W_AR) * 2)   // 104448 B

__global__ __launch_bounds__(256) void qkv_gemm_mma(
    const float* __restrict__ bq, const float* __restrict__ bk, const float* __restrict__ bv)
{
    extern __shared__ half sm[];
    half* sA = sm;                  // [hl][128][GLD2]
    half* sW = sA + 2 * A_AR;       // [hl][64][GLD2]

    const int which = blockIdx.z;
    const float* __restrict__ bias = (which == 0) ? bq : (which == 1) ? bk : bv;
    half* __restrict__ Chi         = (which == 0) ? g_qh : (which == 1) ? g_kh : g_vh;
    half* __restrict__ Clo         = (which == 0) ? g_ql : (which == 1) ? g_kl : g_vl;
    const float oscale = (which == 0) ? 0.17677669529663687f : 1.0f;

    const int tid  = threadIdx.x;
    const int w    = tid >> 5;
    const int lane = tid & 31;
    const int g    = lane >> 2;
    const int c2   = (lane & 3) * 2;
    const int r8   = lane & 7;
    const int sel  = lane >> 3;
    const int rowBase = blockIdx.x * 128;
    const int colBase = blockIdx.y * 64;

    // ---- stage A (128x128) and W (64x128) hi/lo via cp.async ----
    {
        // A: 128 rows x 16 chunks x 2 arrays -> 4096 chunks, 16 iters
        #pragma unroll
        for (int it = 0; it < 8; it++) {
            int i  = tid + it * 256;       // 0..2047 per array
            int r  = i >> 4;
            int k8 = (i & 15) * 8;
            size_t src = (size_t)(rowBase + r) * Dv + k8;
            cp16(sm_u32(&sA[(size_t)0 * A_AR + r * GLD2 + k8]), &g_ah[src]);
            cp16(sm_u32(&sA[(size_t)1 * A_AR + r * GLD2 + k8]), &g_al[src]);
        }
        // W: 64 rows x 16 chunks x 2 arrays -> 2048 chunks, 8 iters
        #pragma unroll
        for (int it = 0; it < 4; it++) {
            int i  = tid + it * 256;       // 0..1023 per array
            int r  = i >> 4;
            int k8 = (i & 15) * 8;
            size_t src = ((size_t)which * Pv + colBase + r) * Dv + k8;
            cp16(sm_u32(&sW[(size_t)0 * W_AR + r * GLD2 + k8]), &g_wh[src]);
            cp16(sm_u32(&sW[(size_t)1 * W_AR + r * GLD2 + k8]), &g_wl[src]);
        }
        cp_commit();
    }

    float acc[8][4];
    #pragma unroll
    for (int nb = 0; nb < 8; nb++)
        acc[nb][0] = acc[nb][1] = acc[nb][2] = acc[nb][3] = 0.f;

    // per-thread ldmatrix base addresses
    const uint32_t aH0 = sm_u32(&sA[(size_t)0 * A_AR + (w * 16 + (sel & 1) * 8 + r8) * GLD2 + (sel >> 1) * 8]);
    const uint32_t aL0 = aH0 + (uint32_t)(A_AR * 2);
    const uint32_t wB0 = sm_u32(&sW[(size_t)(sel >> 1) * W_AR + r8 * GLD2 + (sel & 1) * 8]);

    cp_wait<0>();
    __syncthreads();

    #pragma unroll
    for (int ks = 0; ks < 8; ks++) {
        uint32_t ah[4], al[4];
        ldsm4(ah, aH0 + ks * 32);
        ldsm4(al, aL0 + ks * 32);
        #pragma unroll
        for (int nb = 0; nb < 8; nb++) {
            uint32_t f[4];   // {wh0, wh1, wl0, wl1}
            ldsm4(f, wB0 + (uint32_t)(nb * 8 * GLD2 * 2) + ks * 32);
            mma16816(acc[nb], ah, f);
            mma16816(acc[nb], ah, f + 2);
            mma16816(acc[nb], al, f);
        }
    }

    // epilogue: row decomposition r = (b*Tv + t)*Mv + m
    const int r0 = rowBase + w * 16 + g;
    const int r1 = r0 + 8;
    const int bm0 = ((r0 >> 13) << 4) | (r0 & 15);
    const int t0  = (r0 >> 4) & 511;
    const int bm1 = ((r1 >> 13) << 4) | (r1 & 15);
    const int t1  = (r1 >> 4) & 511;

    size_t dst0, dst1;
    bool wr0 = true, wr1 = true;
    if (which == 0) {
        dst0 = ((size_t)bm0 * Tv + t0) * Pv;
        dst1 = ((size_t)bm1 * Tv + t1) * Pv;
    } else {
        int p0 = g_pos[bm0 * Tv + t0];
        int p1 = g_pos[bm1 * Tv + t1];
        wr0 = (p0 >= 0);
        wr1 = (p1 >= 0);
        dst0 = ((size_t)bm0 * Tv + (wr0 ? p0 : 0)) * Pv;
        dst1 = ((size_t)bm1 * Tv + (wr1 ? p1 : 0)) * Pv;
    }

    #pragma unroll
    for (int nb = 0; nb < 8; nb++) {
        int col = colBase + nb * 8 + c2;
        float bx = __ldg(&bias[col]);
        float by = __ldg(&bias[col + 1]);
        float v00 = (acc[nb][0] + bx) * oscale, v01 = (acc[nb][1] + by) * oscale;
        float v10 = (acc[nb][2] + bx) * oscale, v11 = (acc[nb][3] + by) * oscale;
        uint32_t h0, l0, h1, l1;
        splitpack(v00, v01, h0, l0);
        splitpack(v10, v11, h1, l1);
        if (wr0) {
            *(uint32_t*)&Chi[dst0 + col] = h0;
            *(uint32_t*)&Clo[dst0 + col] = l0;
        }
        if (wr1) {
            *(uint32_t*)&Chi[dst1 + col] = h1;
            *(uint32_t*)&Clo[dst1 + col] = l1;
        }
    }
}

// ---------------------------------------------------------------------------
// Flash attention over COMPACTED keys (unchanged from R14).
// ---------------------------------------------------------------------------
__global__ __launch_bounds__(256) void attn_mma(float* __restrict__ out)
{
    __shared__ half Ksm[2][2][64][40];
    __shared__ half Vsm[2][2][64][40];

    const int tid  = threadIdx.x;
    const int w    = tid >> 5;
    const int lane = tid & 31;
    const int g    = lane >> 2;
    const int c2   = (lane & 3) * 2;
    const int r8   = lane & 7;
    const int sel  = lane >> 3;
    const int qt   = blockIdx.x;
    const int bmh  = blockIdx.y;
    const int h  = bmh & (Hv - 1);
    const int m_ = (bmh >> 3) & (Mv - 1);
    const int b  = bmh >> 7;
    const int bm = b * Mv + m_;

    const size_t qbase   = ((size_t)bm * Tv) * Pv + (size_t)h * Ev;
    const size_t outbase = ((size_t)b * Tv * Mv + m_) * (size_t)Pv + (size_t)h * Ev;
    const int qrow = qt * 128 + w * 16 + g;

    const int nv = g_nv[bm];
    const int ntiles = (nv + 63) >> 6;

    const int srow = tid >> 2;
    const int se8  = (tid & 3) * 8;

    uint32_t kbase[2], vbase[2];
    #pragma unroll
    for (int bf = 0; bf < 2; bf++) {
        kbase[bf] = sm_u32(&Ksm[bf][sel >> 1][r8][(sel & 1) * 8]);
        vbase[bf] = sm_u32(&Vsm[bf][sel >> 1][(sel & 1) * 8 + r8][0]);
    }

    uint32_t qh[2][4], ql[2][4];
    {
        const size_t o0 = qbase + (size_t)qrow * Pv;
        const size_t o1 = o0 + (size_t)8 * Pv;
        #pragma unroll
        for (int ks = 0; ks < 2; ks++) {
            int c = ks * 16 + c2;
            qh[ks][0] = *(const uint32_t*)&g_qh[o0 + c];
            qh[ks][1] = *(const uint32_t*)&g_qh[o1 + c];
            qh[ks][2] = *(const uint32_t*)&g_qh[o0 + c + 8];
            qh[ks][3] = *(const uint32_t*)&g_qh[o1 + c + 8];
            ql[ks][0] = *(const uint32_t*)&g_ql[o0 + c];
            ql[ks][1] = *(const uint32_t*)&g_ql[o1 + c];
            ql[ks][2] = *(const uint32_t*)&g_ql[o0 + c + 8];
            ql[ks][3] = *(const uint32_t*)&g_ql[o1 + c + 8];
        }
    }

    auto stage = [&](int kt, int bf) {
        size_t off = qbase + (size_t)(kt * 64 + srow) * Pv + se8;
        cp16(sm_u32(&Ksm[bf][0][srow][se8]), &g_kh[off]);
        cp16(sm_u32(&Ksm[bf][1][srow][se8]), &g_kl[off]);
        cp16(sm_u32(&Vsm[bf][0][srow][se8]), &g_vh[off]);
        cp16(sm_u32(&Vsm[bf][1][srow][se8]), &g_vl[off]);
    };

    float O[4][4] = {};
    float mrow0 = -1e30f, mrow1 = -1e30f;
    float lrow0 = 0.f,    lrow1 = 0.f;

    if (ntiles > 0) {
        stage(0, 0);
        cp_commit();
    }

    for (int kt = 0; kt < ntiles; kt++) {
        const int cur = kt & 1;
        if (kt + 1 < ntiles) {
            stage(kt + 1, cur ^ 1);
            cp_commit();
            cp_wait<1>();
        } else {
            cp_wait<0>();
        }
        __syncthreads();

        float S[8][4];
        #pragma unroll
        for (int nb = 0; nb < 8; nb++) {
            S[nb][0] = S[nb][1] = S[nb][2] = S[nb][3] = 0.f;
            #pragma unroll
            for (int ks = 0; ks < 2; ks++) {
                uint32_t f[4];
                ldsm4(f, kbase[cur] + (uint32_t)(nb * 640 + ks * 32));
                mma16816(S[nb], qh[ks], f);
                mma16816(S[nb], qh[ks], f + 2);
                mma16816(S[nb], ql[ks], f);
            }
        }

        const int jb = kt * 64;
        float mt0 = -1e30f, mt1 = -1e30f;
        #pragma unroll
        for (int nb = 0; nb < 8; nb++) {
            bool v0 = (jb + nb * 8 + c2)     < nv;
            bool v1 = (jb + nb * 8 + c2 + 1) < nv;
            S[nb][0] = v0 ? S[nb][0] : -1e30f;
            S[nb][1] = v1 ? S[nb][1] : -1e30f;
            S[nb][2] = v0 ? S[nb][2] : -1e30f;
            S[nb][3] = v1 ? S[nb][3] : -1e30f;
            mt0 = fmaxf(mt0, fmaxf(S[nb][0], S[nb][1]));
            mt1 = fmaxf(mt1, fmaxf(S[nb][2], S[nb][3]));
        }
        mt0 = fmaxf(mt0, __shfl_xor_sync(0xffffffffu, mt0, 1));
        mt0 = fmaxf(mt0, __shfl_xor_sync(0xffffffffu, mt0, 2));
        mt1 = fmaxf(mt1, __shfl_xor_sync(0xffffffffu, mt1, 1));
        mt1 = fmaxf(mt1, __shfl_xor_sync(0xffffffffu, mt1, 2));

        float mn0 = fmaxf(mrow0, mt0), mn1 = fmaxf(mrow1, mt1);
        float a0 = __expf(mrow0 - mn0), a1 = __expf(mrow1 - mn1);
        mrow0 = mn0; mrow1 = mn1;

        float rs0 = 0.f, rs1 = 0.f;
        #pragma unroll
        for (int nb = 0; nb < 8; nb++) {
            S[nb][0] = __expf(S[nb][0] - mn0);
            S[nb][1] = __expf(S[nb][1] - mn0);
            S[nb][2] = __expf(S[nb][2] - mn1);
            S[nb][3] = __expf(S[nb][3] - mn1);
            rs0 += S[nb][0] + S[nb][1];
            rs1 += S[nb][2] + S[nb][3];
        }
        rs0 += __shfl_xor_sync(0xffffffffu, rs0, 1);
        rs0 += __shfl_xor_sync(0xffffffffu, rs0, 2);
        rs1 += __shfl_xor_sync(0xffffffffu, rs1, 1);
        rs1 += __shfl_xor_sync(0xffffffffu, rs1, 2);
        lrow0 = lrow0 * a0 + rs0;
        lrow1 = lrow1 * a1 + rs1;
        #pragma unroll
        for (int eb = 0; eb < 4; eb++) {
            O[eb][0] *= a0; O[eb][1] *= a0;
            O[eb][2] *= a1; O[eb][3] *= a1;
        }

        #pragma unroll
        for (int kb = 0; kb < 4; kb++) {
            uint32_t ph[4], pl[4];
            splitpack(S[2 * kb][0],     S[2 * kb][1],     ph[0], pl[0]);
            splitpack(S[2 * kb][2],     S[2 * kb][3],     ph[1], pl[1]);
            splitpack(S[2 * kb + 1][0], S[2 * kb + 1][1], ph[2], pl[2]);
            splitpack(S[2 * kb + 1][2], S[2 * kb + 1][3], ph[3], pl[3]);
            #pragma unroll
            for (int eb = 0; eb < 4; eb++) {
                uint32_t f[4];
                ldsm4t(f, vbase[cur] + (uint32_t)(kb * 1280 + eb * 16));
                mma16816(O[eb], ph, f);
                mma16816(O[eb], ph, f + 2);
                mma16816(O[eb], pl, f);
            }
        }
        __syncthreads();
    }

    float inv0 = (mrow0 > -1e29f) ? (1.f / lrow0) : 0.f;
    float inv1 = (mrow1 > -1e29f) ? (1.f / lrow1) : 0.f;
    float* o0 = &out[outbase + (size_t)qrow * MP];
    float* o1 = o0 + (size_t)8 * MP;
    #pragma unroll
    for (int eb = 0; eb < 4; eb++) {
        int e = eb * 8 + c2;
        o0[e]     = O[eb][0] * inv0;
        o0[e + 1] = O[eb][1] * inv0;
        o1[e]     = O[eb][2] * inv1;
        o1[e + 1] = O[eb][3] * inv1;
    }
}

// ---------------------------------------------------------------------------
// Inputs (metadata order): inp, mask, Wq, bq, Wk, bk, Wv, bv
// ---------------------------------------------------------------------------
extern "C" void kernel_launch(void* const* d_in, const int* in_sizes, int n_in,
                              void* d_out, int out_size)
{
    (void)in_sizes; (void)n_in; (void)out_size;
    const float* inp  = (const float*)d_in[0];
    const int*   mask = (const int*)d_in[1];
    const float* Wq = (const float*)d_in[2];
    const float* bq = (const float*)d_in[3];
    const float* Wk = (const float*)d_in[4];
    const float* bk = (const float*)d_in[5];
    const float* Wv = (const float*)d_in[6];
    const float* bv = (const float*)d_in[7];
    float* out = (float*)d_out;

    static bool attr_done = false;
    if (!attr_done) {
        cudaFuncSetAttribute(qkv_gemm_mma, cudaFuncAttributeMaxDynamicSharedMemorySize, GEMM_SMEM);
        attr_done = true;
    }

    prep_a<<<(ROWS * Dv / 4) / 256, 256>>>(inp);
    prep_w<<<96, 256>>>(Wq, Wk, Wv);
    prep_mask<<<Bv * Mv, 512>>>(mask);

    dim3 ggrid(ROWS / 128, Pv / 64, 3);    // (512, 4, 3)
    qkv_gemm_mma<<<ggrid, 256, GEMM_SMEM>>>(bq, bk, bv);

    dim3 agrid(Tv / 128, Bv * Mv * Hv);    // (4, 1024)
    attn_mma<<<agrid, 256>>>(out);
}

// round 16
// speedup vs baseline: 1.1714x; 1.1714x over previous
#include <cuda_runtime.h>
#include <cuda_fp16.h>
#include <cstdint>

#define Bv 8
#define Tv 512
#define Mv 16
#define Dv 128
#define Pv 256
#define Hv 8
#define Ev 32
#define ROWS (Bv*Tv*Mv)   // 65536
#define MP 4096           // Mv*Pv: element stride between consecutive t (original layout)

// Q in [bm][t][P] layout; K/V COMPACTED per (b,m) in [bm][key][P] layout.
__device__ half g_qh[(size_t)ROWS * Pv];
__device__ half g_ql[(size_t)ROWS * Pv];
__device__ half g_kh[(size_t)ROWS * Pv];
__device__ half g_kl[(size_t)ROWS * Pv];
__device__ half g_vh[(size_t)ROWS * Pv];
__device__ half g_vl[(size_t)ROWS * Pv];
// Pre-split GEMM inputs: A (inp) hi/lo, W transposed [which][c][k] hi/lo.
__device__ half g_ah[(size_t)ROWS * Dv];
__device__ half g_al[(size_t)ROWS * Dv];
__device__ half g_wh[3 * Pv * Dv];
__device__ half g_wl[3 * Pv * Dv];
// Compaction metadata
__device__ int g_pos[Bv * Mv * Tv];   // compacted pos per (bm,t); -1 if masked
__device__ int g_nv[Bv * Mv];         // valid count per (bm)

__device__ __forceinline__ void split2(float x, half& hi, half& lo) {
    hi = __float2half_rn(x);
    lo = __float2half_rn(x - __half2float(hi));
}
__device__ __forceinline__ void splitpack(float x, float y, uint32_t& hi, uint32_t& lo) {
    half hx, lx, hy, ly;
    split2(x, hx, lx);
    split2(y, hy, ly);
    __half2 h = __halves2half2(hx, hy);
    __half2 l = __halves2half2(lx, ly);
    hi = *(uint32_t*)&h;
    lo = *(uint32_t*)&l;
}
__device__ __forceinline__ uint32_t pack2(float x, float y) {
    __half2 h = __floats2half2_rn(x, y);
    return *(uint32_t*)&h;
}
__device__ __forceinline__ void mma16816(float* c, const uint32_t* a, const uint32_t* b) {
    asm volatile(
        "mma.sync.aligned.m16n8k16.row.col.f32.f16.f16.f32 "
        "{%0,%1,%2,%3}, {%4,%5,%6,%7}, {%8,%9}, {%0,%1,%2,%3};\n"
        : "+f"(c[0]), "+f"(c[1]), "+f"(c[2]), "+f"(c[3])
        : "r"(a[0]), "r"(a[1]), "r"(a[2]), "r"(a[3]), "r"(b[0]), "r"(b[1]));
}
__device__ __forceinline__ void ldsm4(uint32_t* r, uint32_t a) {
    asm volatile("ldmatrix.sync.aligned.m8n8.x4.shared.b16 {%0,%1,%2,%3}, [%4];"
        : "=r"(r[0]), "=r"(r[1]), "=r"(r[2]), "=r"(r[3]) : "r"(a));
}
__device__ __forceinline__ void ldsm4t(uint32_t* r, uint32_t a) {
    asm volatile("ldmatrix.sync.aligned.m8n8.x4.trans.shared.b16 {%0,%1,%2,%3}, [%4];"
        : "=r"(r[0]), "=r"(r[1]), "=r"(r[2]), "=r"(r[3]) : "r"(a));
}
__device__ __forceinline__ uint32_t sm_u32(const void* p) {
    return (uint32_t)__cvta_generic_to_shared(p);
}
__device__ __forceinline__ void cp16(uint32_t dst, const void* src) {
    asm volatile("cp.async.cg.shared.global [%0], [%1], 16;" :: "r"(dst), "l"(src));
}
__device__ __forceinline__ void cp_commit() {
    asm volatile("cp.async.commit_group;");
}
template<int N>
__device__ __forceinline__ void cp_wait() {
    asm volatile("cp.async.wait_group %0;" :: "n"(N));
}

// ===========================================================================
// Prep kernels
// ===========================================================================
__global__ __launch_bounds__(256) void prep_a(const float* __restrict__ inp)
{
    size_t idx = (size_t)blockIdx.x * 256 + threadIdx.x;
    float4 a = *(const float4*)&inp[idx * 4];
    uint32_t h0, l0, h1, l1;
    splitpack(a.x, a.y, h0, l0);
    splitpack(a.z, a.w, h1, l1);
    *(uint32_t*)&g_ah[idx * 4]     = h0;
    *(uint32_t*)&g_ah[idx * 4 + 2] = h1;
    *(uint32_t*)&g_al[idx * 4]     = l0;
    *(uint32_t*)&g_al[idx * 4 + 2] = l1;
}

__global__ __launch_bounds__(256) void prep_w(
    const float* __restrict__ Wq, const float* __restrict__ Wk, const float* __restrict__ Wv)
{
    int t = blockIdx.x * 256 + threadIdx.x;
    int which = t / 8192;
    int rem = t - which * 8192;
    int c  = rem >> 5;
    int k4 = (rem & 31) * 4;
    const float* W = (which == 0) ? Wq : (which == 1) ? Wk : Wv;
    float w0 = W[(size_t)(k4 + 0) * Pv + c];
    float w1 = W[(size_t)(k4 + 1) * Pv + c];
    float w2 = W[(size_t)(k4 + 2) * Pv + c];
    float w3 = W[(size_t)(k4 + 3) * Pv + c];
    uint32_t h0, l0, h1, l1;
    splitpack(w0, w1, h0, l0);
    splitpack(w2, w3, h1, l1);
    size_t off = ((size_t)which * Pv + c) * Dv + k4;
    *(uint32_t*)&g_wh[off]     = h0;
    *(uint32_t*)&g_wh[off + 2] = h1;
    *(uint32_t*)&g_wl[off]     = l0;
    *(uint32_t*)&g_wl[off + 2] = l1;
}

// Mask prefix scan per (b,m) + zero-pad compacted K/V tail to tile boundary.
__global__ __launch_bounds__(512) void prep_mask(const int* __restrict__ mask)
{
    __shared__ int wsum[16], woff[16], total_s;
    const int bm = blockIdx.x;
    const int b = bm >> 4, m = bm & 15;
    const int t = threadIdx.x;
    const int lane = t & 31, wid = t >> 5;

    int valid = mask[(size_t)(b * Tv + t) * Mv + m] ? 1 : 0;
    unsigned bal = __ballot_sync(0xffffffffu, valid);
    int wpre = __popc(bal & ((1u << lane) - 1u));
    if (lane == 31) wsum[wid] = wpre + valid;
    __syncthreads();
    if (t == 0) {
        int s = 0;
        for (int i = 0; i < 16; i++) { woff[i] = s; s += wsum[i]; }
        total_s = s;
    }
    __syncthreads();
    const int total = total_s;
    int pos = woff[wid] + wpre;
    g_pos[bm * Tv + t] = valid ? pos : -1;
    if (t == 0) g_nv[bm] = total;

    int padend = (total + 63) & ~63;
    int npad = padend - total;
    uint4 z = make_uint4(0, 0, 0, 0);
    for (int i = t; i < npad * (Pv / 8); i += 512) {
        int rr = total + i / (Pv / 8);
        int e8 = (i % (Pv / 8)) * 8;
        size_t off = ((size_t)bm * Tv + rr) * Pv + e8;
        *(uint4*)&g_kh[off] = z;
        *(uint4*)&g_kl[off] = z;
        *(uint4*)&g_vh[off] = z;
        *(uint4*)&g_vl[off] = z;
    }
}

// ===========================================================================
// QKV GEMM: 128x64 tile, full K=128 staged once, 2 blocks/SM (unchanged R15).
// ===========================================================================
#define GLD2 136
#define A_AR (128 * GLD2)
#define W_AR (64 * GLD2)
#define GEMM_SMEM ((2 * A_AR + 2 * W_AR) * 2)   // 104448 B

__global__ __launch_bounds__(256) void qkv_gemm_mma(
    const float* __restrict__ bq, const float* __restrict__ bk, const float* __restrict__ bv)
{
    extern __shared__ half sm[];
    half* sA = sm;
    half* sW = sA + 2 * A_AR;

    const int which = blockIdx.z;
    const float* __restrict__ bias = (which == 0) ? bq : (which == 1) ? bk : bv;
    half* __restrict__ Chi         = (which == 0) ? g_qh : (which == 1) ? g_kh : g_vh;
    half* __restrict__ Clo         = (which == 0) ? g_ql : (which == 1) ? g_kl : g_vl;
    const float oscale = (which == 0) ? 0.17677669529663687f : 1.0f;

    const int tid  = threadIdx.x;
    const int w    = tid >> 5;
    const int lane = tid & 31;
    const int g    = lane >> 2;
    const int c2   = (lane & 3) * 2;
    const int r8   = lane & 7;
    const int sel  = lane >> 3;
    const int rowBase = blockIdx.x * 128;
    const int colBase = blockIdx.y * 64;

    {
        #pragma unroll
        for (int it = 0; it < 8; it++) {
            int i  = tid + it * 256;
            int r  = i >> 4;
            int k8 = (i & 15) * 8;
            size_t src = (size_t)(rowBase + r) * Dv + k8;
            cp16(sm_u32(&sA[(size_t)0 * A_AR + r * GLD2 + k8]), &g_ah[src]);
            cp16(sm_u32(&sA[(size_t)1 * A_AR + r * GLD2 + k8]), &g_al[src]);
        }
        #pragma unroll
        for (int it = 0; it < 4; it++) {
            int i  = tid + it * 256;
            int r  = i >> 4;
            int k8 = (i & 15) * 8;
            size_t src = ((size_t)which * Pv + colBase + r) * Dv + k8;
            cp16(sm_u32(&sW[(size_t)0 * W_AR + r * GLD2 + k8]), &g_wh[src]);
            cp16(sm_u32(&sW[(size_t)1 * W_AR + r * GLD2 + k8]), &g_wl[src]);
        }
        cp_commit();
    }

    float acc[8][4];
    #pragma unroll
    for (int nb = 0; nb < 8; nb++)
        acc[nb][0] = acc[nb][1] = acc[nb][2] = acc[nb][3] = 0.f;

    const uint32_t aH0 = sm_u32(&sA[(size_t)0 * A_AR + (w * 16 + (sel & 1) * 8 + r8) * GLD2 + (sel >> 1) * 8]);
    const uint32_t aL0 = aH0 + (uint32_t)(A_AR * 2);
    const uint32_t wB0 = sm_u32(&sW[(size_t)(sel >> 1) * W_AR + r8 * GLD2 + (sel & 1) * 8]);

    cp_wait<0>();
    __syncthreads();

    #pragma unroll
    for (int ks = 0; ks < 8; ks++) {
        uint32_t ah[4], al[4];
        ldsm4(ah, aH0 + ks * 32);
        ldsm4(al, aL0 + ks * 32);
        #pragma unroll
        for (int nb = 0; nb < 8; nb++) {
            uint32_t f[4];
            ldsm4(f, wB0 + (uint32_t)(nb * 8 * GLD2 * 2) + ks * 32);
            mma16816(acc[nb], ah, f);
            mma16816(acc[nb], ah, f + 2);
            mma16816(acc[nb], al, f);
        }
    }

    const int r0 = rowBase + w * 16 + g;
    const int r1 = r0 + 8;
    const int bm0 = ((r0 >> 13) << 4) | (r0 & 15);
    const int t0  = (r0 >> 4) & 511;
    const int bm1 = ((r1 >> 13) << 4) | (r1 & 15);
    const int t1  = (r1 >> 4) & 511;

    size_t dst0, dst1;
    bool wr0 = true, wr1 = true;
    if (which == 0) {
        dst0 = ((size_t)bm0 * Tv + t0) * Pv;
        dst1 = ((size_t)bm1 * Tv + t1) * Pv;
    } else {
        int p0 = g_pos[bm0 * Tv + t0];
        int p1 = g_pos[bm1 * Tv + t1];
        wr0 = (p0 >= 0);
        wr1 = (p1 >= 0);
        dst0 = ((size_t)bm0 * Tv + (wr0 ? p0 : 0)) * Pv;
        dst1 = ((size_t)bm1 * Tv + (wr1 ? p1 : 0)) * Pv;
    }

    #pragma unroll
    for (int nb = 0; nb < 8; nb++) {
        int col = colBase + nb * 8 + c2;
        float bx = __ldg(&bias[col]);
        float by = __ldg(&bias[col + 1]);
        float v00 = (acc[nb][0] + bx) * oscale, v01 = (acc[nb][1] + by) * oscale;
        float v10 = (acc[nb][2] + bx) * oscale, v11 = (acc[nb][3] + by) * oscale;
        uint32_t h0, l0, h1, l1;
        splitpack(v00, v01, h0, l0);
        splitpack(v10, v11, h1, l1);
        if (wr0) {
            *(uint32_t*)&Chi[dst0 + col] = h0;
            *(uint32_t*)&Clo[dst0 + col] = l0;
        }
        if (wr1) {
            *(uint32_t*)&Chi[dst1 + col] = h1;
            *(uint32_t*)&Clo[dst1 + col] = l1;
        }
    }
}

// ---------------------------------------------------------------------------
// Flash attention over COMPACTED keys, 2-TERM splits:
//   S = qh·kh + qh·kl    (q_lo dropped, ~2e-4 abs logit error)
//   O += ph·vh + ph·vl   (p_lo dropped, ~2.4e-4 rel error)
// 33% fewer MMAs + half the split ALU vs R14.
// ---------------------------------------------------------------------------
__global__ __launch_bounds__(256) void attn_mma(float* __restrict__ out)
{
    __shared__ half Ksm[2][2][64][40];
    __shared__ half Vsm[2][2][64][40];

    const int tid  = threadIdx.x;
    const int w    = tid >> 5;
    const int lane = tid & 31;
    const int g    = lane >> 2;
    const int c2   = (lane & 3) * 2;
    const int r8   = lane & 7;
    const int sel  = lane >> 3;
    const int qt   = blockIdx.x;
    const int bmh  = blockIdx.y;
    const int h  = bmh & (Hv - 1);
    const int m_ = (bmh >> 3) & (Mv - 1);
    const int b  = bmh >> 7;
    const int bm = b * Mv + m_;

    const size_t qbase   = ((size_t)bm * Tv) * Pv + (size_t)h * Ev;
    const size_t outbase = ((size_t)b * Tv * Mv + m_) * (size_t)Pv + (size_t)h * Ev;
    const int qrow = qt * 128 + w * 16 + g;

    const int nv = g_nv[bm];
    const int ntiles = (nv + 63) >> 6;

    const int srow = tid >> 2;
    const int se8  = (tid & 3) * 8;

    uint32_t kbase[2], vbase[2];
    #pragma unroll
    for (int bf = 0; bf < 2; bf++) {
        kbase[bf] = sm_u32(&Ksm[bf][sel >> 1][r8][(sel & 1) * 8]);
        vbase[bf] = sm_u32(&Vsm[bf][sel >> 1][(sel & 1) * 8 + r8][0]);
    }

    // ---- Q fragments: hi only ----
    uint32_t qh[2][4];
    {
        const size_t o0 = qbase + (size_t)qrow * Pv;
        const size_t o1 = o0 + (size_t)8 * Pv;
        #pragma unroll
        for (int ks = 0; ks < 2; ks++) {
            int c = ks * 16 + c2;
            qh[ks][0] = *(const uint32_t*)&g_qh[o0 + c];
            qh[ks][1] = *(const uint32_t*)&g_qh[o1 + c];
            qh[ks][2] = *(const uint32_t*)&g_qh[o0 + c + 8];
            qh[ks][3] = *(const uint32_t*)&g_qh[o1 + c + 8];
        }
    }

    auto stage = [&](int kt, int bf) {
        size_t off = qbase + (size_t)(kt * 64 + srow) * Pv + se8;
        cp16(sm_u32(&Ksm[bf][0][srow][se8]), &g_kh[off]);
        cp16(sm_u32(&Ksm[bf][1][srow][se8]), &g_kl[off]);
        cp16(sm_u32(&Vsm[bf][0][srow][se8]), &g_vh[off]);
        cp16(sm_u32(&Vsm[bf][1][srow][se8]), &g_vl[off]);
    };

    float O[4][4] = {};
    float mrow0 = -1e30f, mrow1 = -1e30f;
    float lrow0 = 0.f,    lrow1 = 0.f;

    if (ntiles > 0) {
        stage(0, 0);
        cp_commit();
    }

    for (int kt = 0; kt < ntiles; kt++) {
        const int cur = kt & 1;
        if (kt + 1 < ntiles) {
            stage(kt + 1, cur ^ 1);
            cp_commit();
            cp_wait<1>();
        } else {
            cp_wait<0>();
        }
        __syncthreads();

        // ---- S = qh @ (kh + kl)^T ----
        float S[8][4];
        #pragma unroll
        for (int nb = 0; nb < 8; nb++) {
            S[nb][0] = S[nb][1] = S[nb][2] = S[nb][3] = 0.f;
            #pragma unroll
            for (int ks = 0; ks < 2; ks++) {
                uint32_t f[4];   // {kh0, kh1, kl0, kl1}
                ldsm4(f, kbase[cur] + (uint32_t)(nb * 640 + ks * 32));
                mma16816(S[nb], qh[ks], f);
                mma16816(S[nb], qh[ks], f + 2);
            }
        }

        const int jb = kt * 64;
        float mt0 = -1e30f, mt1 = -1e30f;
        #pragma unroll
        for (int nb = 0; nb < 8; nb++) {
            bool v0 = (jb + nb * 8 + c2)     < nv;
            bool v1 = (jb + nb * 8 + c2 + 1) < nv;
            S[nb][0] = v0 ? S[nb][0] : -1e30f;
            S[nb][1] = v1 ? S[nb][1] : -1e30f;
            S[nb][2] = v0 ? S[nb][2] : -1e30f;
            S[nb][3] = v1 ? S[nb][3] : -1e30f;
            mt0 = fmaxf(mt0, fmaxf(S[nb][0], S[nb][1]));
            mt1 = fmaxf(mt1, fmaxf(S[nb][2], S[nb][3]));
        }
        mt0 = fmaxf(mt0, __shfl_xor_sync(0xffffffffu, mt0, 1));
        mt0 = fmaxf(mt0, __shfl_xor_sync(0xffffffffu, mt0, 2));
        mt1 = fmaxf(mt1, __shfl_xor_sync(0xffffffffu, mt1, 1));
        mt1 = fmaxf(mt1, __shfl_xor_sync(0xffffffffu, mt1, 2));

        float mn0 = fmaxf(mrow0, mt0), mn1 = fmaxf(mrow1, mt1);
        float a0 = __expf(mrow0 - mn0), a1 = __expf(mrow1 - mn1);
        mrow0 = mn0; mrow1 = mn1;

        float rs0 = 0.f, rs1 = 0.f;
        #pragma unroll
        for (int nb = 0; nb < 8; nb++) {
            S[nb][0] = __expf(S[nb][0] - mn0);
            S[nb][1] = __expf(S[nb][1] - mn0);
            S[nb][2] = __expf(S[nb][2] - mn1);
            S[nb][3] = __expf(S[nb][3] - mn1);
            rs0 += S[nb][0] + S[nb][1];
            rs1 += S[nb][2] + S[nb][3];
        }
        rs0 += __shfl_xor_sync(0xffffffffu, rs0, 1);
        rs0 += __shfl_xor_sync(0xffffffffu, rs0, 2);
        rs1 += __shfl_xor_sync(0xffffffffu, rs1, 1);
        rs1 += __shfl_xor_sync(0xffffffffu, rs1, 2);
        lrow0 = lrow0 * a0 + rs0;
        lrow1 = lrow1 * a1 + rs1;
        #pragma unroll
        for (int eb = 0; eb < 4; eb++) {
            O[eb][0] *= a0; O[eb][1] *= a0;
            O[eb][2] *= a1; O[eb][3] *= a1;
        }

        // ---- O += ph @ (vh + vl) ----
        #pragma unroll
        for (int kb = 0; kb < 4; kb++) {
            uint32_t ph[4];
            ph[0] = pack2(S[2 * kb][0],     S[2 * kb][1]);
            ph[1] = pack2(S[2 * kb][2],     S[2 * kb][3]);
            ph[2] = pack2(S[2 * kb + 1][0], S[2 * kb + 1][1]);
            ph[3] = pack2(S[2 * kb + 1][2], S[2 * kb + 1][3]);
            #pragma unroll
            for (int eb = 0; eb < 4; eb++) {
                uint32_t f[4];   // {vh0, vh1, vl0, vl1}
                ldsm4t(f, vbase[cur] + (uint32_t)(kb * 1280 + eb * 16));
                mma16816(O[eb], ph, f);
                mma16816(O[eb], ph, f + 2);
            }
        }
        __syncthreads();
    }

    float inv0 = (mrow0 > -1e29f) ? (1.f / lrow0) : 0.f;
    float inv1 = (mrow1 > -1e29f) ? (1.f / lrow1) : 0.f;
    float* o0 = &out[outbase + (size_t)qrow * MP];
    float* o1 = o0 + (size_t)8 * MP;
    #pragma unroll
    for (int eb = 0; eb < 4; eb++) {
        int e = eb * 8 + c2;
        o0[e]     = O[eb][0] * inv0;
        o0[e + 1] = O[eb][1] * inv0;
        o1[e]     = O[eb][2] * inv1;
        o1[e + 1] = O[eb][3] * inv1;
    }
}

// ---------------------------------------------------------------------------
// Inputs (metadata order): inp, mask, Wq, bq, Wk, bk, Wv, bv
// ---------------------------------------------------------------------------
extern "C" void kernel_launch(void* const* d_in, const int* in_sizes, int n_in,
                              void* d_out, int out_size)
{
    (void)in_sizes; (void)n_in; (void)out_size;
    const float* inp  = (const float*)d_in[0];
    const int*   mask = (const int*)d_in[1];
    const float* Wq = (const float*)d_in[2];
    const float* bq = (const float*)d_in[3];
    const float* Wk = (const float*)d_in[4];
    const float* bk = (const float*)d_in[5];
    const float* Wv = (const float*)d_in[6];
    const float* bv = (const float*)d_in[7];
    float* out = (float*)d_out;

    static bool attr_done = false;
    if (!attr_done) {
        cudaFuncSetAttribute(qkv_gemm_mma, cudaFuncAttributeMaxDynamicSharedMemorySize, GEMM_SMEM);
        attr_done = true;
    }

    prep_a<<<(ROWS * Dv / 4) / 256, 256>>>(inp);
    prep_w<<<96, 256>>>(Wq, Wk, Wv);
    prep_mask<<<Bv * Mv, 512>>>(mask);

    dim3 ggrid(ROWS / 128, Pv / 64, 3);    // (512, 4, 3)
    qkv_gemm_mma<<<ggrid, 256, GEMM_SMEM>>>(bq, bk, bv);

    dim3 agrid(Tv / 128, Bv * Mv * Hv);    // (4, 1024)
    attn_mma<<<agrid, 256>>>(out);
}

// round 17
// speedup vs baseline: 1.5358x; 1.3111x over previous
#include <cuda_runtime.h>
#include <cuda_fp16.h>
#include <cstdint>

#define Bv 8
#define Tv 512
#define Mv 16
#define Dv 128
#define Pv 256
#define Hv 8
#define Ev 32
#define ROWS (Bv*Tv*Mv)   // 65536
#define MP 4096           // Mv*Pv: element stride between consecutive t (original layout)

// Q (fp16, pre-scaled) in [bm][t][P]; K/V (fp16) COMPACTED per (b,m) in [bm][key][P].
__device__ half g_qh[(size_t)ROWS * Pv];
__device__ half g_kh[(size_t)ROWS * Pv];
__device__ half g_vh[(size_t)ROWS * Pv];
// Pre-split GEMM inputs: A (inp) hi/lo, W transposed [which][c][k] hi/lo.
__device__ half g_ah[(size_t)ROWS * Dv];
__device__ half g_al[(size_t)ROWS * Dv];
__device__ half g_wh[3 * Pv * Dv];
__device__ half g_wl[3 * Pv * Dv];
// Compaction metadata
__device__ int g_pos[Bv * Mv * Tv];   // compacted pos per (bm,t); -1 if masked
__device__ int g_nv[Bv * Mv];         // valid count per (bm)

__device__ __forceinline__ void split2(float x, half& hi, half& lo) {
    hi = __float2half_rn(x);
    lo = __float2half_rn(x - __half2float(hi));
}
__device__ __forceinline__ void splitpack(float x, float y, uint32_t& hi, uint32_t& lo) {
    half hx, lx, hy, ly;
    split2(x, hx, lx);
    split2(y, hy, ly);
    __half2 h = __halves2half2(hx, hy);
    __half2 l = __halves2half2(lx, ly);
    hi = *(uint32_t*)&h;
    lo = *(uint32_t*)&l;
}
__device__ __forceinline__ uint32_t pack2(float x, float y) {
    __half2 h = __floats2half2_rn(x, y);
    return *(uint32_t*)&h;
}
__device__ __forceinline__ void mma16816(float* c, const uint32_t* a, const uint32_t* b) {
    asm volatile(
        "mma.sync.aligned.m16n8k16.row.col.f32.f16.f16.f32 "
        "{%0,%1,%2,%3}, {%4,%5,%6,%7}, {%8,%9}, {%0,%1,%2,%3};\n"
        : "+f"(c[0]), "+f"(c[1]), "+f"(c[2]), "+f"(c[3])
        : "r"(a[0]), "r"(a[1]), "r"(a[2]), "r"(a[3]), "r"(b[0]), "r"(b[1]));
}
__device__ __forceinline__ void ldsm4(uint32_t* r, uint32_t a) {
    asm volatile("ldmatrix.sync.aligned.m8n8.x4.shared.b16 {%0,%1,%2,%3}, [%4];"
        : "=r"(r[0]), "=r"(r[1]), "=r"(r[2]), "=r"(r[3]) : "r"(a));
}
__device__ __forceinline__ void ldsm4t(uint32_t* r, uint32_t a) {
    asm volatile("ldmatrix.sync.aligned.m8n8.x4.trans.shared.b16 {%0,%1,%2,%3}, [%4];"
        : "=r"(r[0]), "=r"(r[1]), "=r"(r[2]), "=r"(r[3]) : "r"(a));
}
__device__ __forceinline__ uint32_t sm_u32(const void* p) {
    return (uint32_t)__cvta_generic_to_shared(p);
}
__device__ __forceinline__ void cp16(uint32_t dst, const void* src) {
    asm volatile("cp.async.cg.shared.global [%0], [%1], 16;" :: "r"(dst), "l"(src));
}
__device__ __forceinline__ void cp_commit() {
    asm volatile("cp.async.commit_group;");
}
template<int N>
__device__ __forceinline__ void cp_wait() {
    asm volatile("cp.async.wait_group %0;" :: "n"(N));
}

// ===========================================================================
// Prep kernels
// ===========================================================================
__global__ __launch_bounds__(256) void prep_a(const float* __restrict__ inp)
{
    size_t idx = (size_t)blockIdx.x * 256 + threadIdx.x;
    float4 a = *(const float4*)&inp[idx * 4];
    uint32_t h0, l0, h1, l1;
    splitpack(a.x, a.y, h0, l0);
    splitpack(a.z, a.w, h1, l1);
    *(uint32_t*)&g_ah[idx * 4]     = h0;
    *(uint32_t*)&g_ah[idx * 4 + 2] = h1;
    *(uint32_t*)&g_al[idx * 4]     = l0;
    *(uint32_t*)&g_al[idx * 4 + 2] = l1;
}

__global__ __launch_bounds__(256) void prep_w(
    const float* __restrict__ Wq, const float* __restrict__ Wk, const float* __restrict__ Wv)
{
    int t = blockIdx.x * 256 + threadIdx.x;
    int which = t / 8192;
    int rem = t - which * 8192;
    int c  = rem >> 5;
    int k4 = (rem & 31) * 4;
    const float* W = (which == 0) ? Wq : (which == 1) ? Wk : Wv;
    float w0 = W[(size_t)(k4 + 0) * Pv + c];
    float w1 = W[(size_t)(k4 + 1) * Pv + c];
    float w2 = W[(size_t)(k4 + 2) * Pv + c];
    float w3 = W[(size_t)(k4 + 3) * Pv + c];
    uint32_t h0, l0, h1, l1;
    splitpack(w0, w1, h0, l0);
    splitpack(w2, w3, h1, l1);
    size_t off = ((size_t)which * Pv + c) * Dv + k4;
    *(uint32_t*)&g_wh[off]     = h0;
    *(uint32_t*)&g_wh[off + 2] = h1;
    *(uint32_t*)&g_wl[off]     = l0;
    *(uint32_t*)&g_wl[off + 2] = l1;
}

// Mask prefix scan per (b,m) + zero-pad compacted K/V tail to tile boundary.
__global__ __launch_bounds__(512) void prep_mask(const int* __restrict__ mask)
{
    __shared__ int wsum[16], woff[16], total_s;
    const int bm = blockIdx.x;
    const int b = bm >> 4, m = bm & 15;
    const int t = threadIdx.x;
    const int lane = t & 31, wid = t >> 5;

    int valid = mask[(size_t)(b * Tv + t) * Mv + m] ? 1 : 0;
    unsigned bal = __ballot_sync(0xffffffffu, valid);
    int wpre = __popc(bal & ((1u << lane) - 1u));
    if (lane == 31) wsum[wid] = wpre + valid;
    __syncthreads();
    if (t == 0) {
        int s = 0;
        for (int i = 0; i < 16; i++) { woff[i] = s; s += wsum[i]; }
        total_s = s;
    }
    __syncthreads();
    const int total = total_s;
    int pos = woff[wid] + wpre;
    g_pos[bm * Tv + t] = valid ? pos : -1;
    if (t == 0) g_nv[bm] = total;

    int padend = (total + 63) & ~63;
    int npad = padend - total;
    uint4 z = make_uint4(0, 0, 0, 0);
    for (int i = t; i < npad * (Pv / 8); i += 512) {
        int rr = total + i / (Pv / 8);
        int e8 = (i % (Pv / 8)) * 8;
        size_t off = ((size_t)bm * Tv + rr) * Pv + e8;
        *(uint4*)&g_kh[off] = z;
        *(uint4*)&g_vh[off] = z;
    }
}

// ===========================================================================
// QKV GEMM: 128x64 tile, full K=128 staged once, 2 blocks/SM.
// 3-term hi/lo mainloop; epilogue rounds to single fp16 (Q pre-scaled).
// ===========================================================================
#define GLD2 136
#define A_AR (128 * GLD2)
#define W_AR (64 * GLD2)
#define GEMM_SMEM ((2 * A_AR + 2 * W_AR) * 2)   // 104448 B

__global__ __launch_bounds__(256) void qkv_gemm_mma(
    const float* __restrict__ bq, const float* __restrict__ bk, const float* __restrict__ bv)
{
    extern __shared__ half sm[];
    half* sA = sm;
    half* sW = sA + 2 * A_AR;

    const int which = blockIdx.z;
    const float* __restrict__ bias = (which == 0) ? bq : (which == 1) ? bk : bv;
    half* __restrict__ Chi         = (which == 0) ? g_qh : (which == 1) ? g_kh : g_vh;
    const float oscale = (which == 0) ? 0.17677669529663687f : 1.0f;

    const int tid  = threadIdx.x;
    const int w    = tid >> 5;
    const int lane = tid & 31;
    const int g    = lane >> 2;
    const int c2   = (lane & 3) * 2;
    const int r8   = lane & 7;
    const int sel  = lane >> 3;
    const int rowBase = blockIdx.x * 128;
    const int colBase = blockIdx.y * 64;

    {
        #pragma unroll
        for (int it = 0; it < 8; it++) {
            int i  = tid + it * 256;
            int r  = i >> 4;
            int k8 = (i & 15) * 8;
            size_t src = (size_t)(rowBase + r) * Dv + k8;
            cp16(sm_u32(&sA[(size_t)0 * A_AR + r * GLD2 + k8]), &g_ah[src]);
            cp16(sm_u32(&sA[(size_t)1 * A_AR + r * GLD2 + k8]), &g_al[src]);
        }
        #pragma unroll
        for (int it = 0; it < 4; it++) {
            int i  = tid + it * 256;
            int r  = i >> 4;
            int k8 = (i & 15) * 8;
            size_t src = ((size_t)which * Pv + colBase + r) * Dv + k8;
            cp16(sm_u32(&sW[(size_t)0 * W_AR + r * GLD2 + k8]), &g_wh[src]);
            cp16(sm_u32(&sW[(size_t)1 * W_AR + r * GLD2 + k8]), &g_wl[src]);
        }
        cp_commit();
    }

    float acc[8][4];
    #pragma unroll
    for (int nb = 0; nb < 8; nb++)
        acc[nb][0] = acc[nb][1] = acc[nb][2] = acc[nb][3] = 0.f;

    const uint32_t aH0 = sm_u32(&sA[(size_t)0 * A_AR + (w * 16 + (sel & 1) * 8 + r8) * GLD2 + (sel >> 1) * 8]);
    const uint32_t aL0 = aH0 + (uint32_t)(A_AR * 2);
    const uint32_t wB0 = sm_u32(&sW[(size_t)(sel >> 1) * W_AR + r8 * GLD2 + (sel & 1) * 8]);

    cp_wait<0>();
    __syncthreads();

    #pragma unroll
    for (int ks = 0; ks < 8; ks++) {
        uint32_t ah[4], al[4];
        ldsm4(ah, aH0 + ks * 32);
        ldsm4(al, aL0 + ks * 32);
        #pragma unroll
        for (int nb = 0; nb < 8; nb++) {
            uint32_t f[4];
            ldsm4(f, wB0 + (uint32_t)(nb * 8 * GLD2 * 2) + ks * 32);
            mma16816(acc[nb], ah, f);
            mma16816(acc[nb], ah, f + 2);
            mma16816(acc[nb], al, f);
        }
    }

    const int r0 = rowBase + w * 16 + g;
    const int r1 = r0 + 8;
    const int bm0 = ((r0 >> 13) << 4) | (r0 & 15);
    const int t0  = (r0 >> 4) & 511;
    const int bm1 = ((r1 >> 13) << 4) | (r1 & 15);
    const int t1  = (r1 >> 4) & 511;

    size_t dst0, dst1;
    bool wr0 = true, wr1 = true;
    if (which == 0) {
        dst0 = ((size_t)bm0 * Tv + t0) * Pv;
        dst1 = ((size_t)bm1 * Tv + t1) * Pv;
    } else {
        int p0 = g_pos[bm0 * Tv + t0];
        int p1 = g_pos[bm1 * Tv + t1];
        wr0 = (p0 >= 0);
        wr1 = (p1 >= 0);
        dst0 = ((size_t)bm0 * Tv + (wr0 ? p0 : 0)) * Pv;
        dst1 = ((size_t)bm1 * Tv + (wr1 ? p1 : 0)) * Pv;
    }

    #pragma unroll
    for (int nb = 0; nb < 8; nb++) {
        int col = colBase + nb * 8 + c2;
        float bx = __ldg(&bias[col]);
        float by = __ldg(&bias[col + 1]);
        uint32_t h0 = pack2((acc[nb][0] + bx) * oscale, (acc[nb][1] + by) * oscale);
        uint32_t h1 = pack2((acc[nb][2] + bx) * oscale, (acc[nb][3] + by) * oscale);
        if (wr0) *(uint32_t*)&Chi[dst0 + col] = h0;
        if (wr1) *(uint32_t*)&Chi[dst1 + col] = h1;
    }
}

// ---------------------------------------------------------------------------
// Flash attention over COMPACTED keys, single-fp16 Q/K/V:
//   S = qh·kh ; O += ph·vh.  Half the MMAs/ldsm/staging of R16.
// ldmatrix.x4 packs two adjacent key-blocks (S) / e-blocks (O).
// ---------------------------------------------------------------------------
__global__ __launch_bounds__(256) void attn_mma(float* __restrict__ out)
{
    __shared__ half Ksm[2][64][40];   // [buf][key][e]
    __shared__ half Vsm[2][64][40];

    const int tid  = threadIdx.x;
    const int w    = tid >> 5;
    const int lane = tid & 31;
    const int g    = lane >> 2;
    const int c2   = (lane & 3) * 2;
    const int r8   = lane & 7;
    const int sel  = lane >> 3;
    const int qt   = blockIdx.x;
    const int bmh  = blockIdx.y;
    const int h  = bmh & (Hv - 1);
    const int m_ = (bmh >> 3) & (Mv - 1);
    const int b  = bmh >> 7;
    const int bm = b * Mv + m_;

    const size_t qbase   = ((size_t)bm * Tv) * Pv + (size_t)h * Ev;
    const size_t outbase = ((size_t)b * Tv * Mv + m_) * (size_t)Pv + (size_t)h * Ev;
    const int qrow = qt * 128 + w * 16 + g;

    const int nv = g_nv[bm];
    const int ntiles = (nv + 63) >> 6;

    const int srow = tid >> 2;
    const int se8  = (tid & 3) * 8;

    // ldmatrix bases:
    // K (no trans): sel -> (key sub-block, e col block): 4 matrices =
    //   {keys+0 e+0, keys+0 e+8, keys+8 e+0, keys+8 e+8} per np (16 keys)
    // V (trans): sel -> (key sub-block, e block): 4 matrices =
    //   {k0-7 e(2ep), k8-15 e(2ep), k0-7 e(2ep+1), k8-15 e(2ep+1)}
    uint32_t kbase[2], vbase[2];
    #pragma unroll
    for (int bf = 0; bf < 2; bf++) {
        kbase[bf] = sm_u32(&Ksm[bf][(sel >> 1) * 8 + r8][(sel & 1) * 8]);
        vbase[bf] = sm_u32(&Vsm[bf][(sel & 1) * 8 + r8][(sel >> 1) * 8]);
    }

    // ---- Q fragments: fp16 direct ----
    uint32_t qh[2][4];
    {
        const size_t o0 = qbase + (size_t)qrow * Pv;
        const size_t o1 = o0 + (size_t)8 * Pv;
        #pragma unroll
        for (int ks = 0; ks < 2; ks++) {
            int c = ks * 16 + c2;
            qh[ks][0] = *(const uint32_t*)&g_qh[o0 + c];
            qh[ks][1] = *(const uint32_t*)&g_qh[o1 + c];
            qh[ks][2] = *(const uint32_t*)&g_qh[o0 + c + 8];
            qh[ks][3] = *(const uint32_t*)&g_qh[o1 + c + 8];
        }
    }

    auto stage = [&](int kt, int bf) {
        size_t off = qbase + (size_t)(kt * 64 + srow) * Pv + se8;
        cp16(sm_u32(&Ksm[bf][srow][se8]), &g_kh[off]);
        cp16(sm_u32(&Vsm[bf][srow][se8]), &g_vh[off]);
    };

    float O[4][4] = {};
    float mrow0 = -1e30f, mrow1 = -1e30f;
    float lrow0 = 0.f,    lrow1 = 0.f;

    if (ntiles > 0) {
        stage(0, 0);
        cp_commit();
    }

    for (int kt = 0; kt < ntiles; kt++) {
        const int cur = kt & 1;
        if (kt + 1 < ntiles) {
            stage(kt + 1, cur ^ 1);
            cp_commit();
            cp_wait<1>();
        } else {
            cp_wait<0>();
        }
        __syncthreads();

        // ---- S = qh @ kh^T : one ldsm4 covers two key-blocks per ks ----
        float S[8][4];
        #pragma unroll
        for (int np = 0; np < 4; np++) {
            S[2*np][0] = S[2*np][1] = S[2*np][2] = S[2*np][3] = 0.f;
            S[2*np+1][0] = S[2*np+1][1] = S[2*np+1][2] = S[2*np+1][3] = 0.f;
            #pragma unroll
            for (int ks = 0; ks < 2; ks++) {
                uint32_t f[4];   // {k(np16+0-7,e0-7), (..,e8-15), (k+8-15,e0-7), (..,e8-15)}
                ldsm4(f, kbase[cur] + (uint32_t)(np * 1280 + ks * 32));
                mma16816(S[2*np],     qh[ks], f);
                mma16816(S[2*np + 1], qh[ks], f + 2);
            }
        }

        const int jb = kt * 64;
        float mt0 = -1e30f, mt1 = -1e30f;
        #pragma unroll
        for (int nb = 0; nb < 8; nb++) {
            bool v0 = (jb + nb * 8 + c2)     < nv;
            bool v1 = (jb + nb * 8 + c2 + 1) < nv;
            S[nb][0] = v0 ? S[nb][0] : -1e30f;
            S[nb][1] = v1 ? S[nb][1] : -1e30f;
            S[nb][2] = v0 ? S[nb][2] : -1e30f;
            S[nb][3] = v1 ? S[nb][3] : -1e30f;
            mt0 = fmaxf(mt0, fmaxf(S[nb][0], S[nb][1]));
            mt1 = fmaxf(mt1, fmaxf(S[nb][2], S[nb][3]));
        }
        mt0 = fmaxf(mt0, __shfl_xor_sync(0xffffffffu, mt0, 1));
        mt0 = fmaxf(mt0, __shfl_xor_sync(0xffffffffu, mt0, 2));
        mt1 = fmaxf(mt1, __shfl_xor_sync(0xffffffffu, mt1, 1));
        mt1 = fmaxf(mt1, __shfl_xor_sync(0xffffffffu, mt1, 2));

        float mn0 = fmaxf(mrow0, mt0), mn1 = fmaxf(mrow1, mt1);
        float a0 = __expf(mrow0 - mn0), a1 = __expf(mrow1 - mn1);
        mrow0 = mn0; mrow1 = mn1;

        float rs0 = 0.f, rs1 = 0.f;
        #pragma unroll
        for (int nb = 0; nb < 8; nb++) {
            S[nb][0] = __expf(S[nb][0] - mn0);
            S[nb][1] = __expf(S[nb][1] - mn0);
            S[nb][2] = __expf(S[nb][2] - mn1);
            S[nb][3] = __expf(S[nb][3] - mn1);
            rs0 += S[nb][0] + S[nb][1];
            rs1 += S[nb][2] + S[nb][3];
        }
        rs0 += __shfl_xor_sync(0xffffffffu, rs0, 1);
        rs0 += __shfl_xor_sync(0xffffffffu, rs0, 2);
        rs1 += __shfl_xor_sync(0xffffffffu, rs1, 1);
        rs1 += __shfl_xor_sync(0xffffffffu, rs1, 2);
        lrow0 = lrow0 * a0 + rs0;
        lrow1 = lrow1 * a1 + rs1;
        #pragma unroll
        for (int eb = 0; eb < 4; eb++) {
            O[eb][0] *= a0; O[eb][1] *= a0;
            O[eb][2] *= a1; O[eb][3] *= a1;
        }

        // ---- O += ph @ vh : one ldsm4t covers two e-blocks per kb ----
        #pragma unroll
        for (int kb = 0; kb < 4; kb++) {
            uint32_t ph[4];
            ph[0] = pack2(S[2 * kb][0],     S[2 * kb][1]);
            ph[1] = pack2(S[2 * kb][2],     S[2 * kb][3]);
            ph[2] = pack2(S[2 * kb + 1][0], S[2 * kb + 1][1]);
            ph[3] = pack2(S[2 * kb + 1][2], S[2 * kb + 1][3]);
            #pragma unroll
            for (int ep = 0; ep < 2; ep++) {
                uint32_t f[4];   // {k0-7 e(2ep), k8-15 e(2ep), k0-7 e(2ep+1), k8-15 e(2ep+1)}
                ldsm4t(f, vbase[cur] + (uint32_t)(kb * 1280 + ep * 32));
                mma16816(O[2*ep],     ph, f);
                mma16816(O[2*ep + 1], ph, f + 2);
            }
        }
        __syncthreads();
    }

    float inv0 = (mrow0 > -1e29f) ? (1.f / lrow0) : 0.f;
    float inv1 = (mrow1 > -1e29f) ? (1.f / lrow1) : 0.f;
    float* o0 = &out[outbase + (size_t)qrow * MP];
    float* o1 = o0 + (size_t)8 * MP;
    #pragma unroll
    for (int eb = 0; eb < 4; eb++) {
        int e = eb * 8 + c2;
        o0[e]     = O[eb][0] * inv0;
        o0[e + 1] = O[eb][1] * inv0;
        o1[e]     = O[eb][2] * inv1;
        o1[e + 1] = O[eb][3] * inv1;
    }
}

// ---------------------------------------------------------------------------
// Inputs (metadata order): inp, mask, Wq, bq, Wk, bk, Wv, bv
// ---------------------------------------------------------------------------
extern "C" void kernel_launch(void* const* d_in, const int* in_sizes, int n_in,
                              void* d_out, int out_size)
{
    (void)in_sizes; (void)n_in; (void)out_size;
    const float* inp  = (const float*)d_in[0];
    const int*   mask = (const int*)d_in[1];
    const float* Wq = (const float*)d_in[2];
    const float* bq = (const float*)d_in[3];
    const float* Wk = (const float*)d_in[4];
    const float* bk = (const float*)d_in[5];
    const float* Wv = (const float*)d_in[6];
    const float* bv = (const float*)d_in[7];
    float* out = (float*)d_out;

    static bool attr_done = false;
    if (!attr_done) {
        cudaFuncSetAttribute(qkv_gemm_mma, cudaFuncAttributeMaxDynamicSharedMemorySize, GEMM_SMEM);
        attr_done = true;
    }

    prep_a<<<(ROWS * Dv / 4) / 256, 256>>>(inp);
    prep_w<<<96, 256>>>(Wq, Wk, Wv);
    prep_mask<<<Bv * Mv, 512>>>(mask);

    dim3 ggrid(ROWS / 128, Pv / 64, 3);    // (512, 4, 3)
    qkv_gemm_mma<<<ggrid, 256, GEMM_SMEM>>>(bq, bk, bv);

    dim3 agrid(Tv / 128, Bv * Mv * Hv);    // (4, 1024)
    attn_mma<<<agrid, 256>>>(out);
}